// round 9
// baseline (speedup 1.0000x reference)
#include <cuda_runtime.h>
#include <math.h>
#include <stdint.h>

#define BB 2048
#define SS 200
#define DD 128
#define HH 64
#define MASK_SCALE 1e10f
#define NT 256
#define NW (NT / 32)
#define ROWS_PER_WARP (SS / NW)      // 25 (pooling granularity)
#define NSTRIP 13                    // ceil(200/16); strip 12 rows 200..207 garbage-guarded

#define ASTR 528                     // bytes per A row (132 fp32) = 33*16
#define BSTR 288                     // bytes per B row (72 fp32)  = 18*16

// ---- smem byte layout ----
#define A_OFF      0                         // 200*528 = 105600
#define B_OFF      105600                    // 128*288 = 36864 (dead after GEMM)
#define SM_SCRATCH B_OFF                     // pool scratch aliases B: 8*128 f
#define SM_RED     (B_OFF + 4096)            // 8 f (aliases B)
#define SM_RED2    (B_OFF + 4128)            // 8 f (aliases B)
#define SM_ALPHA   142464                    // 256 f
#define SM_CO      143488                    // 64 float2 = 512
#define SMEM_BYTES 144000                    // ~140.6 KB -> 1 CTA/SM

typedef unsigned long long u64;

// Precomputed globals
__device__ uint32_t g_Bt[DD * 72];  // (W1+W2) tf32-rounded fp32 bits, [k][c] pad 72
__device__ float g_Wb[DD * HH];     // W3 - W2
__device__ float g_c[BB * HH];      // tgt @ Wb + W_bias

__device__ __forceinline__ uint32_t smem_u32(const void* p) {
    return (uint32_t)__cvta_generic_to_shared(p);
}
__device__ __forceinline__ void cpa16(void* s, const void* g) {
    asm volatile("cp.async.cg.shared.global [%0], [%1], 16;" :: "r"(smem_u32(s)), "l"(g));
}
#define CP_COMMIT() asm volatile("cp.async.commit_group;")
#define CP_WAIT(n)  asm volatile("cp.async.wait_group %0;" :: "n"(n))

__device__ __forceinline__ uint32_t lds_tf32(uint32_t addr) {
    float f;
    asm volatile("ld.shared.f32 %0, [%1];" : "=f"(f) : "r"(addr));
    uint32_t u;
    asm("cvt.rna.tf32.f32 %0, %1;" : "=r"(u) : "f"(f));
    return u;
}
__device__ __forceinline__ uint32_t lds_u32(uint32_t addr) {
    uint32_t u;
    asm volatile("ld.shared.b32 %0, [%1];" : "=r"(u) : "r"(addr));
    return u;
}
__device__ __forceinline__ void mma_tf32(float* c, const uint32_t* a,
                                         uint32_t b0, uint32_t b1) {
    asm volatile(
        "mma.sync.aligned.m16n8k8.row.col.f32.tf32.tf32.f32 "
        "{%0,%1,%2,%3}, {%4,%5,%6,%7}, {%8,%9}, {%0,%1,%2,%3};"
        : "+f"(c[0]), "+f"(c[1]), "+f"(c[2]), "+f"(c[3])
        : "r"(a[0]), "r"(a[1]), "r"(a[2]), "r"(a[3]), "r"(b0), "r"(b1));
}

__global__ void fold_w_kernel(const float* __restrict__ W) {
    int idx = blockIdx.x * blockDim.x + threadIdx.x;   // over DD*72
    if (idx < DD * 72) {
        int k = idx / 72, n = idx % 72;
        uint32_t r = 0;
        if (n < HH) {
            float w1 = W[k * HH + n];
            float w2 = W[(DD + k) * HH + n];
            float w3 = W[(2 * DD + k) * HH + n];
            g_Wb[k * HH + n] = w3 - w2;
            float wa = w1 + w2;
            asm("cvt.rna.tf32.f32 %0, %1;" : "=r"(r) : "f"(wa));
        }
        g_Bt[idx] = r;
    }
}

__global__ void cvec_kernel(const float* __restrict__ target,
                            const float* __restrict__ W_bias) {
    __shared__ float tgt[DD];
    int b = blockIdx.x;
    for (int i = threadIdx.x; i < DD; i += blockDim.x)
        tgt[i] = target[(size_t)b * DD + i];
    __syncthreads();
    int h = threadIdx.x;
    if (h < HH) {
        float acc = 0.f;
#pragma unroll 8
        for (int d = 0; d < DD; d++)
            acc = fmaf(tgt[d], g_Wb[d * HH + h], acc);
        g_c[b * HH + h] = acc + W_bias[h];
    }
}

__global__ __launch_bounds__(NT, 1)
void ta_main_kernel(const float* __restrict__ his,
                    const float* __restrict__ mask,
                    const float* __restrict__ O,
                    const float* __restrict__ O_bias,
                    float* __restrict__ out) {
    extern __shared__ __align__(16) char sm[];
    float*  alpha = (float*)(sm + SM_ALPHA);
    float2* cO_s  = (float2*)(sm + SM_CO);
    float*  scr   = (float*)(sm + SM_SCRATCH);
    float*  red   = (float*)(sm + SM_RED);
    float*  red2  = (float*)(sm + SM_RED2);

    const int b = blockIdx.x;
    const int tid = threadIdx.x;
    const int wid = tid >> 5;
    const int lane = tid & 31;
    const uint32_t smem_base = smem_u32(sm);

    // ---- Phase 0: group0 = B (L2-hot, fast); group1 = own A strips (DRAM) ----
    for (int i = tid; i < (DD * 72 * 4) / 16; i += NT)
        cpa16(sm + B_OFF + i * 16, (const char*)g_Bt + i * 16);
    CP_COMMIT();

    {
        const int strip0 = wid, strip1 = wid + 8;
#pragma unroll 1
        for (int rnd = 0; rnd < 2; rnd++) {
            const int strip = rnd ? strip1 : strip0;
            if (strip >= NSTRIP) break;
            const int base = strip * 16;
            const int nrows = (base + 16 <= SS) ? 16 : (SS - base);
            const float* hb = his + ((size_t)b * SS + base) * DD + lane * 4;
            char* as = sm + A_OFF + base * ASTR + lane * 16;
#pragma unroll
            for (int j = 0; j < 16; j++) {
                if (j < nrows)
                    cpa16(as + j * ASTR, hb + (size_t)j * DD);
            }
        }
    }
    CP_COMMIT();

    const float ob = O_bias[0];
    if (tid < SS) alpha[tid] = ob - mask[(size_t)b * SS + tid] * MASK_SCALE;
    if (tid < HH) cO_s[tid] = make_float2(g_c[b * HH + tid], O[tid]);

    CP_WAIT(1);          // B done (per-thread); A may still be in flight
    __syncthreads();     // B + alpha pre-bias + cO visible block-wide
    CP_WAIT(0);          // own A strips done
    __syncwarp();

    // ---- Phase 1: tf32 GEMM (dual strip, B-frag reuse) ----
    {
        const int qrow = lane >> 2;        // 0..7
        const int qk   = lane & 3;         // 0..3
        const int strip0 = wid, strip1 = wid + 8;
        const bool two = (strip1 < NSTRIP);

        const uint32_t a0Base = smem_base + A_OFF + (strip0 * 16 + qrow) * ASTR + qk * 4;
        const uint32_t a1Base = smem_base + A_OFF + (strip1 * 16 + qrow) * ASTR + qk * 4;
        const uint32_t bBase  = smem_base + B_OFF + qk * BSTR + qrow * 4;

        float c0[8][4], c1[8][4];
#pragma unroll
        for (int nt = 0; nt < 8; nt++)
#pragma unroll
            for (int q = 0; q < 4; q++) { c0[nt][q] = 0.f; c1[nt][q] = 0.f; }

#pragma unroll
        for (int kk = 0; kk < 16; kk++) {
            const uint32_t ka = kk * 32;               // 8 fp32 per k-step
            uint32_t a0[4], a1[4];
            a0[0] = lds_tf32(a0Base + ka);
            a0[1] = lds_tf32(a0Base + ka + 8 * ASTR);
            a0[2] = lds_tf32(a0Base + ka + 16);
            a0[3] = lds_tf32(a0Base + ka + 8 * ASTR + 16);
            if (two) {
                a1[0] = lds_tf32(a1Base + ka);
                a1[1] = lds_tf32(a1Base + ka + 8 * ASTR);
                a1[2] = lds_tf32(a1Base + ka + 16);
                a1[3] = lds_tf32(a1Base + ka + 8 * ASTR + 16);
            }
            const uint32_t kb = bBase + kk * 8 * BSTR;
#pragma unroll
            for (int nt = 0; nt < 8; nt++) {
                uint32_t b0 = lds_u32(kb + nt * 32);
                uint32_t b1 = lds_u32(kb + nt * 32 + 4 * BSTR);
                mma_tf32(c0[nt], a0, b0, b1);
                if (two) mma_tf32(c1[nt], a1, b0, b1);
            }
        }

        const int cbase = 2 * (lane & 3);
#pragma unroll
        for (int pass = 0; pass < 2; pass++) {
            if (pass == 1 && !two) break;
            float (*c)[4] = pass ? c1 : c0;
            const int strip = pass ? strip1 : strip0;
            float v0 = 0.f, v1 = 0.f;
#pragma unroll
            for (int nt = 0; nt < 8; nt++) {
                int col0 = nt * 8 + cbase;
                float2 co0 = cO_s[col0];
                float2 co1 = cO_s[col0 + 1];
                v0 = fmaf(fmaxf(c[nt][0] + co0.x, 0.f), co0.y, v0);
                v0 = fmaf(fmaxf(c[nt][1] + co1.x, 0.f), co1.y, v0);
                v1 = fmaf(fmaxf(c[nt][2] + co0.x, 0.f), co0.y, v1);
                v1 = fmaf(fmaxf(c[nt][3] + co1.x, 0.f), co1.y, v1);
            }
            v0 += __shfl_xor_sync(0xffffffffu, v0, 1);
            v0 += __shfl_xor_sync(0xffffffffu, v0, 2);
            v1 += __shfl_xor_sync(0xffffffffu, v1, 1);
            v1 += __shfl_xor_sync(0xffffffffu, v1, 2);
            if ((lane & 3) == 0) {
                int s0 = strip * 16 + (lane >> 2);
                if (s0 < SS)     alpha[s0]     = v0 + alpha[s0];
                if (s0 + 8 < SS) alpha[s0 + 8] = v1 + alpha[s0 + 8];
            }
        }
    }
    __syncthreads();

    // ---- Phase 2: softmax over alpha[0..SS) ----
    {
        float vv = (tid < SS) ? alpha[tid] : -INFINITY;
        float m = vv;
#pragma unroll
        for (int off = 16; off > 0; off >>= 1)
            m = fmaxf(m, __shfl_xor_sync(0xffffffffu, m, off));
        if (lane == 0) red[wid] = m;
        __syncthreads();
        m = red[0];
#pragma unroll
        for (int w = 1; w < NW; w++) m = fmaxf(m, red[w]);

        float e = (tid < SS) ? __expf(vv - m) : 0.f;
        float ssum = e;
#pragma unroll
        for (int off = 16; off > 0; off >>= 1)
            ssum += __shfl_xor_sync(0xffffffffu, ssum, off);
        if (lane == 0) red2[wid] = ssum;
        __syncthreads();
        float tot = 0.f;
#pragma unroll
        for (int w = 0; w < NW; w++) tot += red2[w];

        if (tid < SS) alpha[tid] = e / tot;
    }
    __syncthreads();

    // ---- Phase 3: pooling out[b,d] = sum_s attn[s] * his[s,d]  (exact fp32) ----
    {
        const int p = lane;              // d-quad: d = 4p..4p+3
        const int q = wid;               // s-group of 25 rows
        float a0 = 0.f, a1 = 0.f, a2 = 0.f, a3 = 0.f;
        const int sbeg = q * ROWS_PER_WARP;
#pragma unroll 5
        for (int i = 0; i < ROWS_PER_WARP; i++) {
            int s = sbeg + i;
            float4 hv = *(const float4*)(sm + A_OFF + s * ASTR + p * 16);
            float a = alpha[s];
            a0 = fmaf(a, hv.x, a0);
            a1 = fmaf(a, hv.y, a1);
            a2 = fmaf(a, hv.z, a2);
            a3 = fmaf(a, hv.w, a3);
        }
        *(float4*)(scr + q * 128 + p * 4) = make_float4(a0, a1, a2, a3);
        __syncthreads();
        if (tid < DD) {
            float r2 = 0.f;
#pragma unroll
            for (int g2 = 0; g2 < NW; g2++) r2 += scr[g2 * 128 + tid];
            out[(size_t)b * DD + tid] = r2;
        }
    }
}

extern "C" void kernel_launch(void* const* d_in, const int* in_sizes, int n_in,
                              void* d_out, int out_size) {
    const float* his    = (const float*)d_in[0];
    const float* target = (const float*)d_in[1];
    const float* mask   = (const float*)d_in[2];
    const float* W      = (const float*)d_in[3];
    const float* W_bias = (const float*)d_in[4];
    const float* O      = (const float*)d_in[5];
    const float* O_bias = (const float*)d_in[6];
    float* out = (float*)d_out;

    cudaFuncSetAttribute(ta_main_kernel,
                         cudaFuncAttributeMaxDynamicSharedMemorySize, SMEM_BYTES);

    fold_w_kernel<<<(DD * 72 + 255) / 256, 256>>>(W);
    cvec_kernel<<<BB, 128>>>(target, W_bias);
    ta_main_kernel<<<BB, NT, SMEM_BYTES>>>(his, mask, O, O_bias, out);
}

// round 10
// speedup vs baseline: 1.2775x; 1.2775x over previous
#include <cuda_runtime.h>
#include <cuda_fp16.h>
#include <math.h>
#include <stdint.h>

#define BB 2048
#define SS 200
#define DD 128
#define HH 64
#define MASK_SCALE 1e10f
#define NT 256
#define NW (NT / 32)
#define NSTRIP 13                    // ceil(200/16)

#define ASTRIDE 272                  // bytes per A row (136 fp16) = 17*16
#define BSTRIDE 144                  // bytes per B row (72 fp16)  = 9*16

// ---- main-kernel smem layout ----
#define A_OFF      0                         // 200*272 = 54400
#define B_OFF      54400                     // 128*144 = 18432 -> ends 72832
#define SM_MASK    72832                     // 256 f -> 73856
#define SM_CO      73856                     // 64 float2 -> 74368
#define SM_SCR     74368                     // 8*128 f = 4096 -> 78464
#define SM_REDM    78464                     // 8 f -> 78496
#define SM_REDS    78496                     // 8 f -> 78528
#define SMEM_BYTES 78528                     // 76.7 KB -> 2 CTAs/SM

#define PRE_BPB 64
#define PRE_SMEM (128*68*4 + 64*132*4)       // 68608 B

typedef unsigned long long u64;

__device__ __half g_Bh[DD * 72];   // (W1+W2) fp16, [k][c] padded to 72
__device__ float g_c[BB * HH];     // tgt @ (W3-W2) + W_bias

__device__ __forceinline__ uint32_t smem_u32(const void* p) {
    return (uint32_t)__cvta_generic_to_shared(p);
}
__device__ __forceinline__ void cpa16(void* s, const void* g) {
    asm volatile("cp.async.cg.shared.global [%0], [%1], 16;" :: "r"(smem_u32(s)), "l"(g));
}
#define CP_COMMIT() asm volatile("cp.async.commit_group;")
#define CP_WAIT0()  asm volatile("cp.async.wait_group 0;")

__device__ __forceinline__ void ldsm4(uint32_t* r, uint32_t addr) {
    asm volatile("ldmatrix.sync.aligned.m8n8.x4.shared.b16 {%0,%1,%2,%3}, [%4];"
                 : "=r"(r[0]), "=r"(r[1]), "=r"(r[2]), "=r"(r[3]) : "r"(addr));
}
__device__ __forceinline__ void ldsm4t(uint32_t* r, uint32_t addr) {
    asm volatile("ldmatrix.sync.aligned.m8n8.x4.trans.shared.b16 {%0,%1,%2,%3}, [%4];"
                 : "=r"(r[0]), "=r"(r[1]), "=r"(r[2]), "=r"(r[3]) : "r"(addr));
}
__device__ __forceinline__ void mma16816(float* c, const uint32_t* a,
                                         uint32_t b0, uint32_t b1) {
    asm volatile(
        "mma.sync.aligned.m16n8k16.row.col.f32.f16.f16.f32 "
        "{%0,%1,%2,%3}, {%4,%5,%6,%7}, {%8,%9}, {%0,%1,%2,%3};"
        : "+f"(c[0]), "+f"(c[1]), "+f"(c[2]), "+f"(c[3])
        : "r"(a[0]), "r"(a[1]), "r"(a[2]), "r"(a[3]), "r"(b0), "r"(b1));
}

// ---- prologue: fold W into g_Bh (block 0) + cvec GEMM g_c (all blocks) ----
__global__ __launch_bounds__(256, 1)
void prologue_kernel(const float* __restrict__ W,
                     const float* __restrict__ target,
                     const float* __restrict__ W_bias) {
    extern __shared__ float ps[];
    float* Wb_s  = ps;                 // [128][68]
    float* tgt_s = ps + 128 * 68;      // [64][132]
    const int tid = threadIdx.x;
    const int b0 = blockIdx.x * PRE_BPB;

    for (int i = tid; i < DD * HH; i += 256) {
        int d = i >> 6, h = i & 63;
        float w2 = W[(DD + d) * HH + h];
        float w3 = W[(2 * DD + d) * HH + h];
        Wb_s[d * 68 + h] = w3 - w2;
        if (blockIdx.x == 0) {
            float w1 = W[d * HH + h];
            g_Bh[d * 72 + h] = __float2half_rn(w1 + w2);
        }
    }
    if (blockIdx.x == 0) {
        for (int i = tid; i < DD * 8; i += 256)
            g_Bh[(i >> 3) * 72 + 64 + (i & 7)] = __float2half_rn(0.f);
    }
    for (int i = tid; i < PRE_BPB * DD; i += 256) {
        int r = i >> 7, d = i & 127;
        tgt_s[r * 132 + d] = target[(size_t)(b0 + r) * DD + d];
    }
    __syncthreads();

    const int tx = tid & 15, ty = tid >> 4;
    float acc[4][4];
#pragma unroll
    for (int i = 0; i < 4; i++)
#pragma unroll
        for (int j = 0; j < 4; j++) acc[i][j] = 0.f;
#pragma unroll 4
    for (int k = 0; k < DD; k++) {
        float tv[4], wv[4];
#pragma unroll
        for (int i = 0; i < 4; i++) tv[i] = tgt_s[(4 * ty + i) * 132 + k];
#pragma unroll
        for (int j = 0; j < 4; j++) wv[j] = Wb_s[k * 68 + 4 * tx + j];
#pragma unroll
        for (int i = 0; i < 4; i++)
#pragma unroll
            for (int j = 0; j < 4; j++)
                acc[i][j] = fmaf(tv[i], wv[j], acc[i][j]);
    }
#pragma unroll
    for (int i = 0; i < 4; i++)
#pragma unroll
        for (int j = 0; j < 4; j++)
            g_c[(size_t)(b0 + 4 * ty + i) * HH + 4 * tx + j] = acc[i][j] + W_bias[4 * tx + j];
}

// ---- main kernel ----
__global__ __launch_bounds__(NT, 2)
void ta_main_kernel(const float* __restrict__ his,
                    const float* __restrict__ mask,
                    const float* __restrict__ O,
                    const float* __restrict__ O_bias,
                    float* __restrict__ out) {
    extern __shared__ __align__(16) char sm[];
    float*  mask_s = (float*)(sm + SM_MASK);
    float2* cO_s   = (float2*)(sm + SM_CO);
    float*  scr    = (float*)(sm + SM_SCR);
    float*  redm   = (float*)(sm + SM_REDM);
    float*  reds   = (float*)(sm + SM_REDS);

    const int b = blockIdx.x;
    const int tid = threadIdx.x;
    const int wid = tid >> 5;
    const int lane = tid & 31;
    const uint32_t smem_base = smem_u32(sm);

    // ---- Phase 0a: B via cp.async; mask + cO direct ----
    for (int i = tid; i < 18432 / 16; i += NT)
        cpa16(sm + B_OFF + i * 16, (const char*)g_Bh + i * 16);
    CP_COMMIT();

    const float ob = O_bias[0];
    if (tid < SS) mask_s[tid] = mask[(size_t)b * SS + tid];
    if (tid < HH) cO_s[tid] = make_float2(g_c[b * HH + tid], O[tid]);

    CP_WAIT0();
    __syncthreads();     // B + mask + cO visible block-wide

    // ---- Phase 0b: own-strip A loading (warp-local), 8-deep LDG batches ----
    {
        const int k0 = 4 * lane;
#pragma unroll 1
        for (int rnd = 0; rnd < 2; rnd++) {
            const int strip = wid + rnd * 8;
            if (strip >= NSTRIP) break;
            const int base = strip * 16;
            const int nrows = (base + 16 <= SS) ? 16 : (SS - base);
            const float* hb = his + ((size_t)b * SS + base) * DD + k0;
#pragma unroll 1
            for (int g0 = 0; g0 < nrows; g0 += 8) {
                float4 v[8];
#pragma unroll
                for (int j = 0; j < 8; j++)
                    if (g0 + j < nrows) v[j] = *(const float4*)(hb + (size_t)(g0 + j) * DD);
#pragma unroll
                for (int j = 0; j < 8; j++)
                    if (g0 + j < nrows) {
                        int s = base + g0 + j;
                        __half2 p01 = __floats2half2_rn(v[j].x, v[j].y);
                        __half2 p23 = __floats2half2_rn(v[j].z, v[j].w);
                        u64 hp = ((u64)*(uint32_t*)&p23 << 32) | *(uint32_t*)&p01;
                        *(u64*)(sm + A_OFF + s * ASTRIDE + k0 * 2) = hp;
                    }
            }
        }
    }
    __syncwarp();

    // ---- Phase 1: GEMM (dual strip, B-frag reuse) + fused softmax/pool ----
    {
        const int g = lane >> 3;
        const int r = lane & 7;
        const int arow_l = r + (g & 1) * 8;
        const int acol_l = (g >> 1) * 16;
        const int brow_l = r + (g & 1) * 8;
        const uint32_t aB = smem_base + A_OFF;
        const uint32_t bH = smem_base + B_OFF + brow_l * BSTRIDE + (g >> 1) * 16;

        const int strip0 = wid;
        const int strip1 = wid + 8;
        const bool two = (strip1 < NSTRIP);
        const bool hasHi1 = two && (strip1 * 16 + 8 < SS);   // strip12: false

        float c0[8][4], c1[8][4];
#pragma unroll
        for (int nt = 0; nt < 8; nt++)
#pragma unroll
            for (int q = 0; q < 4; q++) { c0[nt][q] = 0.f; c1[nt][q] = 0.f; }

        const uint32_t Ab0 = aB + (strip0 * 16 + arow_l) * ASTRIDE + acol_l;
        const uint32_t Ab1 = aB + (strip1 * 16 + arow_l) * ASTRIDE + acol_l;

#pragma unroll
        for (int kk = 0; kk < 8; kk++) {
            uint32_t a0[4], a1[4];
            ldsm4(a0, Ab0 + kk * 32);
            if (two) ldsm4(a1, Ab1 + kk * 32);
            const uint32_t koff = kk * 16 * BSTRIDE;
#pragma unroll
            for (int np2 = 0; np2 < 4; np2++) {
                uint32_t bf[4];
                ldsm4t(bf, bH + koff + np2 * 32);
                mma16816(c0[2 * np2],     a0, bf[0], bf[1]);
                mma16816(c0[2 * np2 + 1], a0, bf[2], bf[3]);
                if (two) {
                    mma16816(c1[2 * np2],     a1, bf[0], bf[1]);
                    mma16816(c1[2 * np2 + 1], a1, bf[2], bf[3]);
                }
            }
        }

        // logits (4 per lane): strip0 rows qr, qr+8; strip1 rows qr, qr+8
        const int qr = lane >> 2;
        const int cbase = 2 * (lane & 3);
        float v00 = 0.f, v01 = 0.f, v10 = 0.f, v11 = 0.f;
#pragma unroll
        for (int nt = 0; nt < 8; nt++) {
            int col0 = nt * 8 + cbase;
            float2 co0 = cO_s[col0];
            float2 co1 = cO_s[col0 + 1];
            v00 = fmaf(fmaxf(c0[nt][0] + co0.x, 0.f), co0.y, v00);
            v00 = fmaf(fmaxf(c0[nt][1] + co1.x, 0.f), co1.y, v00);
            v01 = fmaf(fmaxf(c0[nt][2] + co0.x, 0.f), co0.y, v01);
            v01 = fmaf(fmaxf(c0[nt][3] + co1.x, 0.f), co1.y, v01);
            v10 = fmaf(fmaxf(c1[nt][0] + co0.x, 0.f), co0.y, v10);
            v10 = fmaf(fmaxf(c1[nt][1] + co1.x, 0.f), co1.y, v10);
            v11 = fmaf(fmaxf(c1[nt][2] + co0.x, 0.f), co0.y, v11);
            v11 = fmaf(fmaxf(c1[nt][3] + co1.x, 0.f), co1.y, v11);
        }
        // quad reduce (lanes in quad end with identical values)
        v00 += __shfl_xor_sync(0xffffffffu, v00, 1);
        v00 += __shfl_xor_sync(0xffffffffu, v00, 2);
        v01 += __shfl_xor_sync(0xffffffffu, v01, 1);
        v01 += __shfl_xor_sync(0xffffffffu, v01, 2);
        v10 += __shfl_xor_sync(0xffffffffu, v10, 1);
        v10 += __shfl_xor_sync(0xffffffffu, v10, 2);
        v11 += __shfl_xor_sync(0xffffffffu, v11, 1);
        v11 += __shfl_xor_sync(0xffffffffu, v11, 2);

        const int s00 = strip0 * 16 + qr;
        const int s01 = s00 + 8;
        const int s10 = strip1 * 16 + qr;
        const int s11 = s10 + 8;
        v00 += ob - mask_s[s00] * MASK_SCALE;
        v01 += ob - mask_s[s01] * MASK_SCALE;
        if (two)    v10 += ob - mask_s[s10] * MASK_SCALE; else v10 = -INFINITY;
        if (hasHi1) v11 += ob - mask_s[s11] * MASK_SCALE; else v11 = -INFINITY;

        // warp max
        float m = fmaxf(fmaxf(v00, v01), fmaxf(v10, v11));
#pragma unroll
        for (int off = 16; off > 0; off >>= 1)
            m = fmaxf(m, __shfl_xor_sync(0xffffffffu, m, off));

        float e00 = __expf(v00 - m);
        float e01 = __expf(v01 - m);
        float e10 = two ? __expf(v10 - m) : 0.f;
        float e11 = hasHi1 ? __expf(v11 - m) : 0.f;

        // warp sum of exps (count each quad once)
        float sp = ((lane & 3) == 0) ? (e00 + e01 + e10 + e11) : 0.f;
#pragma unroll
        for (int off = 16; off > 0; off >>= 1)
            sp += __shfl_xor_sync(0xffffffffu, sp, off);

        if (lane == 0) { redm[wid] = m; reds[wid] = sp; }

        // warp-local pooling of own rows; lane owns d = 4*lane..4*lane+3
        float a0 = 0.f, a1 = 0.f, a2 = 0.f, a3 = 0.f;
#pragma unroll
        for (int rr = 0; rr < 8; rr++) {
            float er00 = __shfl_sync(0xffffffffu, e00, 4 * rr);
            float er01 = __shfl_sync(0xffffffffu, e01, 4 * rr);
            {
                uint2 hv = *(uint2*)(sm + A_OFF + (strip0 * 16 + rr) * ASTRIDE + lane * 8);
                float2 f01 = __half22float2(*(__half2*)&hv.x);
                float2 f23 = __half22float2(*(__half2*)&hv.y);
                a0 = fmaf(er00, f01.x, a0); a1 = fmaf(er00, f01.y, a1);
                a2 = fmaf(er00, f23.x, a2); a3 = fmaf(er00, f23.y, a3);
            }
            {
                uint2 hv = *(uint2*)(sm + A_OFF + (strip0 * 16 + 8 + rr) * ASTRIDE + lane * 8);
                float2 f01 = __half22float2(*(__half2*)&hv.x);
                float2 f23 = __half22float2(*(__half2*)&hv.y);
                a0 = fmaf(er01, f01.x, a0); a1 = fmaf(er01, f01.y, a1);
                a2 = fmaf(er01, f23.x, a2); a3 = fmaf(er01, f23.y, a3);
            }
            if (two) {
                float er10 = __shfl_sync(0xffffffffu, e10, 4 * rr);
                uint2 hv = *(uint2*)(sm + A_OFF + (strip1 * 16 + rr) * ASTRIDE + lane * 8);
                float2 f01 = __half22float2(*(__half2*)&hv.x);
                float2 f23 = __half22float2(*(__half2*)&hv.y);
                a0 = fmaf(er10, f01.x, a0); a1 = fmaf(er10, f01.y, a1);
                a2 = fmaf(er10, f23.x, a2); a3 = fmaf(er10, f23.y, a3);
            }
            if (hasHi1) {
                float er11 = __shfl_sync(0xffffffffu, e11, 4 * rr);
                uint2 hv = *(uint2*)(sm + A_OFF + (strip1 * 16 + 8 + rr) * ASTRIDE + lane * 8);
                float2 f01 = __half22float2(*(__half2*)&hv.x);
                float2 f23 = __half22float2(*(__half2*)&hv.y);
                a0 = fmaf(er11, f01.x, a0); a1 = fmaf(er11, f01.y, a1);
                a2 = fmaf(er11, f23.x, a2); a3 = fmaf(er11, f23.y, a3);
            }
        }
        *(float4*)(scr + wid * 128 + lane * 4) = make_float4(a0, a1, a2, a3);
    }
    __syncthreads();

    // ---- Phase 2: combine (online-softmax merge) ----
    if (tid < DD) {
        float M = redm[0];
#pragma unroll
        for (int q = 1; q < NW; q++) M = fmaxf(M, redm[q]);
        float T = 0.f, acc = 0.f;
#pragma unroll
        for (int q = 0; q < NW; q++) {
            float f = __expf(redm[q] - M);
            T = fmaf(reds[q], f, T);
            acc = fmaf(scr[q * 128 + tid], f, acc);
        }
        out[(size_t)b * DD + tid] = acc / T;
    }
}

extern "C" void kernel_launch(void* const* d_in, const int* in_sizes, int n_in,
                              void* d_out, int out_size) {
    const float* his    = (const float*)d_in[0];
    const float* target = (const float*)d_in[1];
    const float* mask   = (const float*)d_in[2];
    const float* W      = (const float*)d_in[3];
    const float* W_bias = (const float*)d_in[4];
    const float* O      = (const float*)d_in[5];
    const float* O_bias = (const float*)d_in[6];
    float* out = (float*)d_out;

    cudaFuncSetAttribute(prologue_kernel,
                         cudaFuncAttributeMaxDynamicSharedMemorySize, PRE_SMEM);
    cudaFuncSetAttribute(ta_main_kernel,
                         cudaFuncAttributeMaxDynamicSharedMemorySize, SMEM_BYTES);

    prologue_kernel<<<BB / PRE_BPB, 256, PRE_SMEM>>>(W, target, W_bias);
    ta_main_kernel<<<BB, NT, SMEM_BYTES>>>(his, mask, O, O_bias, out);
}

// round 11
// speedup vs baseline: 1.3684x; 1.0712x over previous
#include <cuda_runtime.h>
#include <cuda_fp16.h>
#include <math.h>
#include <stdint.h>

#define BB 2048
#define SS 200
#define DD 128
#define HH 64
#define MASK_SCALE 1e10f
#define NT 256
#define NW (NT / 32)
#define NSTRIP 13                    // ceil(200/16)

#define ASTRIDE 272                  // bytes per A row (136 fp16) = 17*16
#define BSTRIDE 144                  // bytes per B row (72 fp16)  = 9*16

// ---- main-kernel smem layout ----
#define A_OFF      0                         // 200*272 = 54400
#define B_OFF      54400                     // 128*144 = 18432 -> ends 72832
#define SM_MASK    72832                     // 256 f -> 73856
#define SM_CO      73856                     // 64 float2 -> 74368
#define SM_SCR     74368                     // 8*128 f = 4096 -> 78464
#define SM_REDM    78464                     // 8 f -> 78496
#define SM_REDS    78496                     // 8 f -> 78528
#define SMEM_BYTES 78528                     // 76.7 KB -> 2 CTAs/SM

typedef unsigned long long u64;

__device__ __half g_Bh[DD * 72];   // (W1+W2) fp16, [k][c]; pad cols stay 0
__device__ float g_Wb[DD * HH];    // W3 - W2
__device__ float g_c[BB * HH];     // tgt @ Wb + W_bias

__device__ __forceinline__ uint32_t smem_u32(const void* p) {
    return (uint32_t)__cvta_generic_to_shared(p);
}
__device__ __forceinline__ void cpa16(void* s, const void* g) {
    asm volatile("cp.async.cg.shared.global [%0], [%1], 16;" :: "r"(smem_u32(s)), "l"(g));
}
#define CP_COMMIT() asm volatile("cp.async.commit_group;")
#define CP_WAIT0()  asm volatile("cp.async.wait_group 0;")

__device__ __forceinline__ void ldsm4(uint32_t* r, uint32_t addr) {
    asm volatile("ldmatrix.sync.aligned.m8n8.x4.shared.b16 {%0,%1,%2,%3}, [%4];"
                 : "=r"(r[0]), "=r"(r[1]), "=r"(r[2]), "=r"(r[3]) : "r"(addr));
}
__device__ __forceinline__ void ldsm4t(uint32_t* r, uint32_t addr) {
    asm volatile("ldmatrix.sync.aligned.m8n8.x4.trans.shared.b16 {%0,%1,%2,%3}, [%4];"
                 : "=r"(r[0]), "=r"(r[1]), "=r"(r[2]), "=r"(r[3]) : "r"(addr));
}
__device__ __forceinline__ void mma16816(float* c, const uint32_t* a,
                                         uint32_t b0, uint32_t b1) {
    asm volatile(
        "mma.sync.aligned.m16n8k16.row.col.f32.f16.f16.f32 "
        "{%0,%1,%2,%3}, {%4,%5,%6,%7}, {%8,%9}, {%0,%1,%2,%3};"
        : "+f"(c[0]), "+f"(c[1]), "+f"(c[2]), "+f"(c[3])
        : "r"(a[0]), "r"(a[1]), "r"(a[2]), "r"(a[3]), "r"(b0), "r"(b1));
}

__global__ void fold_w_kernel(const float* __restrict__ W) {
    int idx = blockIdx.x * blockDim.x + threadIdx.x;   // DD*HH
    if (idx < DD * HH) {
        int k = idx >> 6, c = idx & 63;
        float w1 = W[k * HH + c];
        float w2 = W[(DD + k) * HH + c];
        float w3 = W[(2 * DD + k) * HH + c];
        g_Wb[k * HH + c] = w3 - w2;
        g_Bh[k * 72 + c] = __float2half_rn(w1 + w2);
    }
}

__global__ void cvec_kernel(const float* __restrict__ target,
                            const float* __restrict__ W_bias) {
    __shared__ float tgt[DD];
    int b = blockIdx.x;
    for (int i = threadIdx.x; i < DD; i += blockDim.x)
        tgt[i] = target[(size_t)b * DD + i];
    __syncthreads();
    int h = threadIdx.x;
    if (h < HH) {
        float acc = 0.f;
#pragma unroll 8
        for (int d = 0; d < DD; d++)
            acc = fmaf(tgt[d], g_Wb[d * HH + h], acc);
        g_c[b * HH + h] = acc + W_bias[h];
    }
}

// ---- main kernel ----
__global__ __launch_bounds__(NT, 2)
void ta_main_kernel(const float* __restrict__ his,
                    const float* __restrict__ mask,
                    const float* __restrict__ O,
                    const float* __restrict__ O_bias,
                    float* __restrict__ out) {
    extern __shared__ __align__(16) char sm[];
    float*  mask_s = (float*)(sm + SM_MASK);
    float2* cO_s   = (float2*)(sm + SM_CO);
    float*  scr    = (float*)(sm + SM_SCR);
    float*  redm   = (float*)(sm + SM_REDM);
    float*  reds   = (float*)(sm + SM_REDS);

    const int b = blockIdx.x;
    const int tid = threadIdx.x;
    const int wid = tid >> 5;
    const int lane = tid & 31;
    const uint32_t smem_base = smem_u32(sm);

    // ---- Phase 0: ALL DRAM traffic issued up front ----
    // B via cp.async (fire-and-forget)
    for (int i = tid; i < 18432 / 16; i += NT)
        cpa16(sm + B_OFF + i * 16, (const char*)g_Bh + i * 16);
    CP_COMMIT();

    const float ob = O_bias[0];
    if (tid < SS) mask_s[tid] = mask[(size_t)b * SS + tid];
    if (tid < HH) cO_s[tid] = make_float2(g_c[b * HH + tid], O[tid]);

    // Own-strip A loading (warp-local, 8-deep LDG batches) — BEFORE B wait.
    {
        const int k0 = 4 * lane;
#pragma unroll 1
        for (int rnd = 0; rnd < 2; rnd++) {
            const int strip = wid + rnd * 8;
            if (strip >= NSTRIP) break;
            const int base = strip * 16;
            const int nrows = (base + 16 <= SS) ? 16 : (SS - base);
            const float* hb = his + ((size_t)b * SS + base) * DD + k0;
#pragma unroll 1
            for (int g0 = 0; g0 < nrows; g0 += 8) {
                float4 v[8];
#pragma unroll
                for (int j = 0; j < 8; j++)
                    if (g0 + j < nrows) v[j] = *(const float4*)(hb + (size_t)(g0 + j) * DD);
#pragma unroll
                for (int j = 0; j < 8; j++)
                    if (g0 + j < nrows) {
                        int s = base + g0 + j;
                        __half2 p01 = __floats2half2_rn(v[j].x, v[j].y);
                        __half2 p23 = __floats2half2_rn(v[j].z, v[j].w);
                        u64 hp = ((u64)*(uint32_t*)&p23 << 32) | *(uint32_t*)&p01;
                        *(u64*)(sm + A_OFF + s * ASTRIDE + k0 * 2) = hp;
                    }
            }
        }
    }

    CP_WAIT0();          // B landed (this thread's groups)
    __syncthreads();     // B + mask + cO visible; own A rows warp-visible already

    // ---- Phase 1: GEMM (dual strip, B-frag reuse) + fused softmax/pool ----
    {
        const int g = lane >> 3;
        const int r = lane & 7;
        const int arow_l = r + (g & 1) * 8;
        const int acol_l = (g >> 1) * 16;
        const int brow_l = r + (g & 1) * 8;
        const uint32_t aB = smem_base + A_OFF;
        const uint32_t bH = smem_base + B_OFF + brow_l * BSTRIDE + (g >> 1) * 16;

        const int strip0 = wid;
        const int strip1 = wid + 8;
        const bool two = (strip1 < NSTRIP);
        const bool hasHi1 = two && (strip1 * 16 + 8 < SS);   // strip12: false

        float c0[8][4], c1[8][4];
#pragma unroll
        for (int nt = 0; nt < 8; nt++)
#pragma unroll
            for (int q = 0; q < 4; q++) { c0[nt][q] = 0.f; c1[nt][q] = 0.f; }

        const uint32_t Ab0 = aB + (strip0 * 16 + arow_l) * ASTRIDE + acol_l;
        const uint32_t Ab1 = aB + (strip1 * 16 + arow_l) * ASTRIDE + acol_l;

#pragma unroll
        for (int kk = 0; kk < 8; kk++) {
            uint32_t a0[4], a1[4];
            ldsm4(a0, Ab0 + kk * 32);
            if (two) ldsm4(a1, Ab1 + kk * 32);
            const uint32_t koff = kk * 16 * BSTRIDE;
#pragma unroll
            for (int np2 = 0; np2 < 4; np2++) {
                uint32_t bf[4];
                ldsm4t(bf, bH + koff + np2 * 32);
                mma16816(c0[2 * np2],     a0, bf[0], bf[1]);
                mma16816(c0[2 * np2 + 1], a0, bf[2], bf[3]);
                if (two) {
                    mma16816(c1[2 * np2],     a1, bf[0], bf[1]);
                    mma16816(c1[2 * np2 + 1], a1, bf[2], bf[3]);
                }
            }
        }

        // logits (4 per lane): strip0 rows qr, qr+8; strip1 rows qr, qr+8
        const int qr = lane >> 2;
        const int cbase = 2 * (lane & 3);
        float v00 = 0.f, v01 = 0.f, v10 = 0.f, v11 = 0.f;
#pragma unroll
        for (int nt = 0; nt < 8; nt++) {
            int col0 = nt * 8 + cbase;
            float2 co0 = cO_s[col0];
            float2 co1 = cO_s[col0 + 1];
            v00 = fmaf(fmaxf(c0[nt][0] + co0.x, 0.f), co0.y, v00);
            v00 = fmaf(fmaxf(c0[nt][1] + co1.x, 0.f), co1.y, v00);
            v01 = fmaf(fmaxf(c0[nt][2] + co0.x, 0.f), co0.y, v01);
            v01 = fmaf(fmaxf(c0[nt][3] + co1.x, 0.f), co1.y, v01);
            v10 = fmaf(fmaxf(c1[nt][0] + co0.x, 0.f), co0.y, v10);
            v10 = fmaf(fmaxf(c1[nt][1] + co1.x, 0.f), co1.y, v10);
            v11 = fmaf(fmaxf(c1[nt][2] + co0.x, 0.f), co0.y, v11);
            v11 = fmaf(fmaxf(c1[nt][3] + co1.x, 0.f), co1.y, v11);
        }
        v00 += __shfl_xor_sync(0xffffffffu, v00, 1);
        v00 += __shfl_xor_sync(0xffffffffu, v00, 2);
        v01 += __shfl_xor_sync(0xffffffffu, v01, 1);
        v01 += __shfl_xor_sync(0xffffffffu, v01, 2);
        v10 += __shfl_xor_sync(0xffffffffu, v10, 1);
        v10 += __shfl_xor_sync(0xffffffffu, v10, 2);
        v11 += __shfl_xor_sync(0xffffffffu, v11, 1);
        v11 += __shfl_xor_sync(0xffffffffu, v11, 2);

        const int s00 = strip0 * 16 + qr;
        const int s01 = s00 + 8;
        const int s10 = strip1 * 16 + qr;
        const int s11 = s10 + 8;
        v00 += ob - mask_s[s00] * MASK_SCALE;
        v01 += ob - mask_s[s01] * MASK_SCALE;
        if (two)    v10 += ob - mask_s[s10] * MASK_SCALE; else v10 = -INFINITY;
        if (hasHi1) v11 += ob - mask_s[s11] * MASK_SCALE; else v11 = -INFINITY;

        float m = fmaxf(fmaxf(v00, v01), fmaxf(v10, v11));
#pragma unroll
        for (int off = 16; off > 0; off >>= 1)
            m = fmaxf(m, __shfl_xor_sync(0xffffffffu, m, off));

        float e00 = __expf(v00 - m);
        float e01 = __expf(v01 - m);
        float e10 = two ? __expf(v10 - m) : 0.f;
        float e11 = hasHi1 ? __expf(v11 - m) : 0.f;

        float sp = ((lane & 3) == 0) ? (e00 + e01 + e10 + e11) : 0.f;
#pragma unroll
        for (int off = 16; off > 0; off >>= 1)
            sp += __shfl_xor_sync(0xffffffffu, sp, off);

        if (lane == 0) { redm[wid] = m; reds[wid] = sp; }

        // warp-local pooling of own rows; lane owns d = 4*lane..4*lane+3
        float a0 = 0.f, a1 = 0.f, a2 = 0.f, a3 = 0.f;
#pragma unroll
        for (int rr = 0; rr < 8; rr++) {
            float er00 = __shfl_sync(0xffffffffu, e00, 4 * rr);
            float er01 = __shfl_sync(0xffffffffu, e01, 4 * rr);
            {
                uint2 hv = *(uint2*)(sm + A_OFF + (strip0 * 16 + rr) * ASTRIDE + lane * 8);
                float2 f01 = __half22float2(*(__half2*)&hv.x);
                float2 f23 = __half22float2(*(__half2*)&hv.y);
                a0 = fmaf(er00, f01.x, a0); a1 = fmaf(er00, f01.y, a1);
                a2 = fmaf(er00, f23.x, a2); a3 = fmaf(er00, f23.y, a3);
            }
            {
                uint2 hv = *(uint2*)(sm + A_OFF + (strip0 * 16 + 8 + rr) * ASTRIDE + lane * 8);
                float2 f01 = __half22float2(*(__half2*)&hv.x);
                float2 f23 = __half22float2(*(__half2*)&hv.y);
                a0 = fmaf(er01, f01.x, a0); a1 = fmaf(er01, f01.y, a1);
                a2 = fmaf(er01, f23.x, a2); a3 = fmaf(er01, f23.y, a3);
            }
            if (two) {
                float er10 = __shfl_sync(0xffffffffu, e10, 4 * rr);
                uint2 hv = *(uint2*)(sm + A_OFF + (strip1 * 16 + rr) * ASTRIDE + lane * 8);
                float2 f01 = __half22float2(*(__half2*)&hv.x);
                float2 f23 = __half22float2(*(__half2*)&hv.y);
                a0 = fmaf(er10, f01.x, a0); a1 = fmaf(er10, f01.y, a1);
                a2 = fmaf(er10, f23.x, a2); a3 = fmaf(er10, f23.y, a3);
            }
            if (hasHi1) {
                float er11 = __shfl_sync(0xffffffffu, e11, 4 * rr);
                uint2 hv = *(uint2*)(sm + A_OFF + (strip1 * 16 + 8 + rr) * ASTRIDE + lane * 8);
                float2 f01 = __half22float2(*(__half2*)&hv.x);
                float2 f23 = __half22float2(*(__half2*)&hv.y);
                a0 = fmaf(er11, f01.x, a0); a1 = fmaf(er11, f01.y, a1);
                a2 = fmaf(er11, f23.x, a2); a3 = fmaf(er11, f23.y, a3);
            }
        }
        *(float4*)(scr + wid * 128 + lane * 4) = make_float4(a0, a1, a2, a3);
    }
    __syncthreads();

    // ---- Phase 2: combine (online-softmax merge) ----
    if (tid < DD) {
        float M = redm[0];
#pragma unroll
        for (int q = 1; q < NW; q++) M = fmaxf(M, redm[q]);
        float T = 0.f, acc = 0.f;
#pragma unroll
        for (int q = 0; q < NW; q++) {
            float f = __expf(redm[q] - M);
            T = fmaf(reds[q], f, T);
            acc = fmaf(scr[q * 128 + tid], f, acc);
        }
        out[(size_t)b * DD + tid] = acc / T;
    }
}

extern "C" void kernel_launch(void* const* d_in, const int* in_sizes, int n_in,
                              void* d_out, int out_size) {
    const float* his    = (const float*)d_in[0];
    const float* target = (const float*)d_in[1];
    const float* mask   = (const float*)d_in[2];
    const float* W      = (const float*)d_in[3];
    const float* W_bias = (const float*)d_in[4];
    const float* O      = (const float*)d_in[5];
    const float* O_bias = (const float*)d_in[6];
    float* out = (float*)d_out;

    cudaFuncSetAttribute(ta_main_kernel,
                         cudaFuncAttributeMaxDynamicSharedMemorySize, SMEM_BYTES);

    fold_w_kernel<<<(DD * HH + 255) / 256, 256>>>(W);
    cvec_kernel<<<BB, 128>>>(target, W_bias);
    ta_main_kernel<<<BB, NT, SMEM_BYTES>>>(his, mask, O, O_bias, out);
}